// round 1
// baseline (speedup 1.0000x reference)
#include <cuda_runtime.h>
#include <math.h>

#define N_ATOMS 4096
#define F_DIM   256
#define NH      8
#define DH      32
#define NG      128
#define QKV_LD  768

// Scratch (no allocations allowed)
__device__ float g_qkv[N_ATOMS * QKV_LD];   // per row: [0:256)=Q [256:512)=K [512:768)=V
__device__ float g_segsum[NG * F_DIM];      // segment-summed attention output
__device__ float g_h1[NG * F_DIM];          // after Wo1

// ---------------------------------------------------------------------------
// Fused QKV projection GEMM: C[4096 x 768] = x[4096 x 256] @ [Wq|Wk|Wv]^T + b
// BM=64 BN=64 BK=32, 256 threads, 4x4 microtile, smem transposed (k-major)
// ---------------------------------------------------------------------------
__global__ void proj_gemm(const float* __restrict__ x,
                          const float* __restrict__ Wq, const float* __restrict__ bq,
                          const float* __restrict__ Wk, const float* __restrict__ bk,
                          const float* __restrict__ Wv, const float* __restrict__ bv)
{
    __shared__ float As[32][64];   // As[kk][row]  = x[n0+row][k0+kk]
    __shared__ float Bs[32][68];   // Bs[kk][jj]   = W[jl+jj][k0+kk]  (padded)

    const int tid = threadIdx.x;
    const int ti  = tid >> 4;          // 0..15
    const int tj  = tid & 15;          // 0..15
    const int n0  = blockIdx.y * 64;
    const int j0  = blockIdx.x * 64;   // 0..704
    const int sel = j0 >> 8;
    const float* __restrict__ W = (sel == 0) ? Wq : (sel == 1 ? Wk : Wv);
    const float* __restrict__ b = (sel == 0) ? bq : (sel == 1 ? bk : bv);
    const int jl = j0 & 255;

    float acc[4][4] = {};

    for (int k0 = 0; k0 < 256; k0 += 32) {
        #pragma unroll
        for (int r = 0; r < 2; r++) {
            int idx = tid + r * 256;
            int row = idx >> 3;        // 0..63
            int c4  = idx & 7;         // 0..7
            float4 a = *(const float4*)&x[(n0 + row) * 256 + k0 + c4 * 4];
            As[c4 * 4 + 0][row] = a.x;
            As[c4 * 4 + 1][row] = a.y;
            As[c4 * 4 + 2][row] = a.z;
            As[c4 * 4 + 3][row] = a.w;
            float4 w = *(const float4*)&W[(jl + row) * 256 + k0 + c4 * 4];
            Bs[c4 * 4 + 0][row] = w.x;
            Bs[c4 * 4 + 1][row] = w.y;
            Bs[c4 * 4 + 2][row] = w.z;
            Bs[c4 * 4 + 3][row] = w.w;
        }
        __syncthreads();
        #pragma unroll
        for (int kk = 0; kk < 32; kk++) {
            float4 a4 = *(const float4*)&As[kk][ti * 4];
            float4 b4 = *(const float4*)&Bs[kk][tj * 4];
            float av[4] = {a4.x, a4.y, a4.z, a4.w};
            float bv2[4] = {b4.x, b4.y, b4.z, b4.w};
            #pragma unroll
            for (int u = 0; u < 4; u++)
                #pragma unroll
                for (int v = 0; v < 4; v++)
                    acc[u][v] += av[u] * bv2[v];
        }
        __syncthreads();
    }

    float4 bias4 = *(const float4*)&b[jl + tj * 4];
    #pragma unroll
    for (int u = 0; u < 4; u++) {
        float4 o;
        o.x = acc[u][0] + bias4.x;
        o.y = acc[u][1] + bias4.y;
        o.z = acc[u][2] + bias4.z;
        o.w = acc[u][3] + bias4.w;
        *(float4*)&g_qkv[(n0 + ti * 4 + u) * QKV_LD + j0 + tj * 4] = o;
    }
}

// ---------------------------------------------------------------------------
__global__ void zero_segsum()
{
    g_segsum[blockIdx.x * 256 + threadIdx.x] = 0.0f;
}

// ---------------------------------------------------------------------------
// Block-diagonal attention + fused segment-sum.
// One block per row n; 8 warps = 8 heads; lane = head dim.
// ---------------------------------------------------------------------------
__global__ void attn_kernel(const int* __restrict__ seg)
{
    __shared__ int s_start, s_end, s_g;
    const int n   = blockIdx.x;
    const int tid = threadIdx.x;

    if (tid == 0) {
        int gid = seg[n];
        s_g = gid;
        int lo = 0, hi = N_ATOMS;                     // lower bound
        while (lo < hi) { int mid = (lo + hi) >> 1; if (seg[mid] < gid) lo = mid + 1; else hi = mid; }
        s_start = lo;
        lo = n + 1; hi = N_ATOMS;                      // upper bound
        while (lo < hi) { int mid = (lo + hi) >> 1; if (seg[mid] <= gid) lo = mid + 1; else hi = mid; }
        s_end = lo;
    }
    __syncthreads();

    const int h    = tid >> 5;
    const int lane = tid & 31;
    const int col  = h * DH + lane;

    const float q = g_qkv[n * QKV_LD + col];
    float acc = 0.0f;
    const int start = s_start, end = s_end, gid = s_g;

    for (int m = start; m < end; m++) {
        float kd = g_qkv[m * QKV_LD + 256 + col];
        float vd = g_qkv[m * QKV_LD + 512 + col];
        float p = q * kd;
        #pragma unroll
        for (int off = 16; off; off >>= 1)
            p += __shfl_xor_sync(0xffffffffu, p, off);
        float s = p / (1.0f + expf(-p));     // silu
        acc += s * vd;
    }
    atomicAdd(&g_segsum[gid * 256 + col], acc);
}

// ---------------------------------------------------------------------------
// Small GEMM on [128,256] x [256,256]^T:
//   mode 0: out = A @ W^T + cnt_g * b            (Wo1 + commuted segment bias)
//   mode 1: out = silu(A @ W^T + b)              (Wo2 + final activation)
// grid (NG, 8); block 256 = 8 warps; warp handles 4 output columns (dot+reduce)
// ---------------------------------------------------------------------------
__global__ void small_gemm(const float* __restrict__ A, const float* __restrict__ W,
                           const float* __restrict__ b, float* __restrict__ out,
                           const int* __restrict__ seg, int mode)
{
    __shared__ float a_sh[256];
    __shared__ float biasScale;
    const int g   = blockIdx.x;
    const int jc  = blockIdx.y;
    const int tid = threadIdx.x;

    a_sh[tid] = A[g * 256 + tid];
    if (tid == 0) {
        float sc = 1.0f;
        if (mode == 0) {
            int lo = 0, hi = N_ATOMS;
            while (lo < hi) { int mid = (lo + hi) >> 1; if (seg[mid] < g) lo = mid + 1; else hi = mid; }
            int st = lo;
            lo = st; hi = N_ATOMS;
            while (lo < hi) { int mid = (lo + hi) >> 1; if (seg[mid] <= g) lo = mid + 1; else hi = mid; }
            sc = (float)(lo - st);
        }
        biasScale = sc;
    }
    __syncthreads();

    const int w    = tid >> 5;
    const int lane = tid & 31;

    #pragma unroll
    for (int u = 0; u < 4; u++) {
        int j = jc * 32 + w * 4 + u;
        float sum = 0.0f;
        #pragma unroll
        for (int kc = 0; kc < 8; kc++) {
            int k = kc * 32 + lane;
            sum += a_sh[k] * W[j * 256 + k];
        }
        #pragma unroll
        for (int off = 16; off; off >>= 1)
            sum += __shfl_xor_sync(0xffffffffu, sum, off);
        if (lane == 0) {
            float val = sum + biasScale * b[j];
            if (mode == 1) val = val / (1.0f + expf(-val));
            out[g * 256 + j] = val;
        }
    }
}

// ---------------------------------------------------------------------------
extern "C" void kernel_launch(void* const* d_in, const int* in_sizes, int n_in,
                              void* d_out, int out_size)
{
    const float* x    = (const float*)d_in[0];
    const int*   elem = (const int*)d_in[1];
    const int*   seg  = elem + N_ATOMS;        // elem_index[1]
    const float* Wq   = (const float*)d_in[2];
    const float* bq   = (const float*)d_in[3];
    const float* Wk   = (const float*)d_in[4];
    const float* bk   = (const float*)d_in[5];
    const float* Wv   = (const float*)d_in[6];
    const float* bv   = (const float*)d_in[7];
    const float* Wo1  = (const float*)d_in[8];
    const float* bo1  = (const float*)d_in[9];
    const float* Wo2  = (const float*)d_in[10];
    const float* bo2  = (const float*)d_in[11];
    float* out = (float*)d_out;

    float *p_segsum, *p_h1;
    cudaGetSymbolAddress((void**)&p_segsum, g_segsum);
    cudaGetSymbolAddress((void**)&p_h1, g_h1);

    proj_gemm<<<dim3(12, 64), 256>>>(x, Wq, bq, Wk, bk, Wv, bv);
    zero_segsum<<<NG, 256>>>();
    attn_kernel<<<N_ATOMS, 256>>>(seg);
    small_gemm<<<dim3(NG, 8), 256>>>(p_segsum, Wo1, bo1, p_h1, seg, 0);
    small_gemm<<<dim3(NG, 8), 256>>>(p_h1, Wo2, bo2, out, seg, 1);
}

// round 2
// speedup vs baseline: 1.5226x; 1.5226x over previous
#include <cuda_runtime.h>
#include <math.h>

#define N_ATOMS 4096
#define F_DIM   256
#define NH      8
#define DH      32
#define NG      128
#define QKV_LD  768

// Scratch (no allocations allowed)
__device__ float g_qkv[N_ATOMS * QKV_LD];   // per row: [0:256)=Q [256:512)=K [512:768)=V
__device__ float g_segsum[NG * F_DIM];      // segment-summed attention output
__device__ float g_h1[NG * F_DIM];          // after Wo1

__device__ __forceinline__ float to_tf32(float x) {
    asm("cvt.rna.tf32.f32 %0, %0;" : "+f"(x));
    return x;
}

__device__ __forceinline__ void mma_tf32(float c[4], const unsigned a[4], const unsigned b[2]) {
    asm volatile(
        "mma.sync.aligned.m16n8k8.row.col.f32.tf32.tf32.f32 "
        "{%0,%1,%2,%3}, {%4,%5,%6,%7}, {%8,%9}, {%0,%1,%2,%3};"
        : "+f"(c[0]), "+f"(c[1]), "+f"(c[2]), "+f"(c[3])
        : "r"(a[0]), "r"(a[1]), "r"(a[2]), "r"(a[3]), "r"(b[0]), "r"(b[1]));
}

// ---------------------------------------------------------------------------
// Fused QKV projection GEMM (TF32 tensor cores):
// C[4096 x 768] = x[4096 x 256] @ [Wq|Wk|Wv]^T + b
// BM=128 BN=64 BK=32, 256 threads = 8 warps (4x2), warp tile 32x32.
// ---------------------------------------------------------------------------
__global__ __launch_bounds__(256) void proj_gemm(
        const float* __restrict__ x,
        const float* __restrict__ Wq, const float* __restrict__ bq,
        const float* __restrict__ Wk, const float* __restrict__ bk,
        const float* __restrict__ Wv, const float* __restrict__ bv)
{
    __shared__ float As[128][36];   // [row][k], pad 4 -> conflict-free frag loads
    __shared__ float Bs[64][36];    // [j][k]

    const int tid  = threadIdx.x;
    const int warp = tid >> 5;
    const int lane = tid & 31;
    const int grp  = lane >> 2;     // 0..7
    const int tig  = lane & 3;      // 0..3
    const int wm   = warp >> 1;     // 0..3  (rows wm*32)
    const int wn   = warp & 1;      // 0..1  (cols wn*32)

    const int n0 = blockIdx.y * 128;
    const int j0 = blockIdx.x * 64;
    const int sel = j0 >> 8;
    const float* __restrict__ W = (sel == 0) ? Wq : (sel == 1 ? Wk : Wv);
    const float* __restrict__ b = (sel == 0) ? bq : (sel == 1 ? bk : bv);
    const int jl = j0 & 255;

    float c[2][4][4] = {};

    for (int k0 = 0; k0 < 256; k0 += 32) {
        // load A tile (128x32) -> 4 float4 per thread, convert to tf32
        #pragma unroll
        for (int it = 0; it < 4; it++) {
            int idx = tid + it * 256;
            int row = idx >> 3;
            int c4  = idx & 7;
            float4 a = *(const float4*)&x[(n0 + row) * 256 + k0 + c4 * 4];
            a.x = to_tf32(a.x); a.y = to_tf32(a.y); a.z = to_tf32(a.z); a.w = to_tf32(a.w);
            *(float4*)&As[row][c4 * 4] = a;
        }
        // load B tile (64x32)
        #pragma unroll
        for (int it = 0; it < 2; it++) {
            int idx = tid + it * 256;
            int row = idx >> 3;
            int c4  = idx & 7;
            float4 w = *(const float4*)&W[(jl + row) * 256 + k0 + c4 * 4];
            w.x = to_tf32(w.x); w.y = to_tf32(w.y); w.z = to_tf32(w.z); w.w = to_tf32(w.w);
            *(float4*)&Bs[row][c4 * 4] = w;
        }
        __syncthreads();

        #pragma unroll
        for (int ks = 0; ks < 4; ks++) {
            const int kb = ks * 8;
            unsigned af[2][4];
            #pragma unroll
            for (int mt = 0; mt < 2; mt++) {
                int rb = wm * 32 + mt * 16;
                af[mt][0] = __float_as_uint(As[rb + grp    ][kb + tig    ]);
                af[mt][1] = __float_as_uint(As[rb + 8 + grp][kb + tig    ]);
                af[mt][2] = __float_as_uint(As[rb + grp    ][kb + tig + 4]);
                af[mt][3] = __float_as_uint(As[rb + 8 + grp][kb + tig + 4]);
            }
            unsigned bf[4][2];
            #pragma unroll
            for (int nt = 0; nt < 4; nt++) {
                int cb = wn * 32 + nt * 8;
                bf[nt][0] = __float_as_uint(Bs[cb + grp][kb + tig    ]);
                bf[nt][1] = __float_as_uint(Bs[cb + grp][kb + tig + 4]);
            }
            #pragma unroll
            for (int mt = 0; mt < 2; mt++)
                #pragma unroll
                for (int nt = 0; nt < 4; nt++)
                    mma_tf32(c[mt][nt], af[mt], bf[nt]);
        }
        __syncthreads();
    }

    // epilogue: add bias, store float2 pairs
    #pragma unroll
    for (int mt = 0; mt < 2; mt++) {
        int r0 = n0 + wm * 32 + mt * 16 + grp;
        int r1 = r0 + 8;
        #pragma unroll
        for (int nt = 0; nt < 4; nt++) {
            int jj  = j0 + wn * 32 + nt * 8 + tig * 2;
            int jlb = jl + wn * 32 + nt * 8 + tig * 2;
            float b0 = b[jlb], b1 = b[jlb + 1];
            float2 o0 = make_float2(c[mt][nt][0] + b0, c[mt][nt][1] + b1);
            float2 o1 = make_float2(c[mt][nt][2] + b0, c[mt][nt][3] + b1);
            *(float2*)&g_qkv[r0 * QKV_LD + jj] = o0;
            *(float2*)&g_qkv[r1 * QKV_LD + jj] = o1;
        }
    }
}

// ---------------------------------------------------------------------------
__global__ void zero_segsum()
{
    g_segsum[blockIdx.x * 256 + threadIdx.x] = 0.0f;
}

// ---------------------------------------------------------------------------
// Block-diagonal attention + fused segment-sum.
// One block per row n; 8 warps = 8 heads; lane = head dim.
// ---------------------------------------------------------------------------
__global__ __launch_bounds__(256) void attn_kernel(const int* __restrict__ seg)
{
    __shared__ int s_start, s_end, s_g;
    const int n   = blockIdx.x;
    const int tid = threadIdx.x;

    if (tid == 0) {
        int gid = seg[n];
        s_g = gid;
        int lo = 0, hi = N_ATOMS;
        while (lo < hi) { int mid = (lo + hi) >> 1; if (seg[mid] < gid) lo = mid + 1; else hi = mid; }
        s_start = lo;
        lo = n + 1; hi = N_ATOMS;
        while (lo < hi) { int mid = (lo + hi) >> 1; if (seg[mid] <= gid) lo = mid + 1; else hi = mid; }
        s_end = lo;
    }
    __syncthreads();

    const int h    = tid >> 5;
    const int lane = tid & 31;
    const int col  = h * DH + lane;

    const float q = g_qkv[n * QKV_LD + col];
    float acc = 0.0f;
    const int start = s_start, end = s_end, gid = s_g;

    #pragma unroll 2
    for (int m = start; m < end; m++) {
        float kd = __ldg(&g_qkv[m * QKV_LD + 256 + col]);
        float vd = __ldg(&g_qkv[m * QKV_LD + 512 + col]);
        float p = q * kd;
        #pragma unroll
        for (int off = 16; off; off >>= 1)
            p += __shfl_xor_sync(0xffffffffu, p, off);
        float s = __fdividef(p, 1.0f + __expf(-p));     // silu
        acc += s * vd;
    }
    atomicAdd(&g_segsum[gid * 256 + col], acc);
}

// ---------------------------------------------------------------------------
// Small tiled GEMM on [128,256] x [256,256]^T:
//   mode 0: out = A @ W^T + cnt_g * b            (Wo1 + commuted segment bias)
//   mode 1: out = silu(A @ W^T + b)              (Wo2 + final activation)
// BM=32 BN=64 BK=32, 256 threads, 2x4 microtile. grid (4, 4).
// ---------------------------------------------------------------------------
__global__ __launch_bounds__(256) void small_gemm(
        const float* __restrict__ A, const float* __restrict__ W,
        const float* __restrict__ b, float* __restrict__ out,
        const int* __restrict__ seg, int mode)
{
    __shared__ float As[32][34];    // [kk][row]
    __shared__ float Bs[32][68];    // [kk][col]
    __shared__ float s_cnt[32];

    const int tid = threadIdx.x;
    const int ti  = tid >> 4;       // 0..15 -> rows ti*2
    const int tj  = tid & 15;       // 0..15 -> cols tj*4
    const int g0  = blockIdx.y * 32;
    const int j0  = blockIdx.x * 64;

    if (tid < 32) {
        float sc = 1.0f;
        if (mode == 0) {
            int g = g0 + tid;
            int lo = 0, hi = N_ATOMS;
            while (lo < hi) { int mid = (lo + hi) >> 1; if (seg[mid] < g) lo = mid + 1; else hi = mid; }
            int st = lo;
            hi = N_ATOMS;
            while (lo < hi) { int mid = (lo + hi) >> 1; if (seg[mid] <= g) lo = mid + 1; else hi = mid; }
            sc = (float)(lo - st);
        }
        s_cnt[tid] = sc;
    }

    float acc[2][4] = {};

    for (int k0 = 0; k0 < 256; k0 += 32) {
        {
            int row = tid >> 3;
            int c4  = tid & 7;
            float4 a = *(const float4*)&A[(g0 + row) * 256 + k0 + c4 * 4];
            As[c4 * 4 + 0][row] = a.x;
            As[c4 * 4 + 1][row] = a.y;
            As[c4 * 4 + 2][row] = a.z;
            As[c4 * 4 + 3][row] = a.w;
        }
        #pragma unroll
        for (int it = 0; it < 2; it++) {
            int idx = tid + it * 256;
            int row = idx >> 3;
            int c4  = idx & 7;
            float4 w = *(const float4*)&W[(j0 + row) * 256 + k0 + c4 * 4];
            Bs[c4 * 4 + 0][row] = w.x;
            Bs[c4 * 4 + 1][row] = w.y;
            Bs[c4 * 4 + 2][row] = w.z;
            Bs[c4 * 4 + 3][row] = w.w;
        }
        __syncthreads();
        #pragma unroll
        for (int kk = 0; kk < 32; kk++) {
            float2 a2 = *(const float2*)&As[kk][ti * 2];
            float4 b4 = *(const float4*)&Bs[kk][tj * 4];
            acc[0][0] += a2.x * b4.x; acc[0][1] += a2.x * b4.y;
            acc[0][2] += a2.x * b4.z; acc[0][3] += a2.x * b4.w;
            acc[1][0] += a2.y * b4.x; acc[1][1] += a2.y * b4.y;
            acc[1][2] += a2.y * b4.z; acc[1][3] += a2.y * b4.w;
        }
        __syncthreads();
    }

    #pragma unroll
    for (int u = 0; u < 2; u++) {
        int g = g0 + ti * 2 + u;
        float cnt = s_cnt[ti * 2 + u];
        #pragma unroll
        for (int v = 0; v < 4; v++) {
            int j = j0 + tj * 4 + v;
            float val = acc[u][v] + cnt * b[j];
            if (mode == 1) val = __fdividef(val, 1.0f + __expf(-val));
            out[g * 256 + j] = val;
        }
    }
}

// ---------------------------------------------------------------------------
extern "C" void kernel_launch(void* const* d_in, const int* in_sizes, int n_in,
                              void* d_out, int out_size)
{
    const float* x    = (const float*)d_in[0];
    const int*   elem = (const int*)d_in[1];
    const int*   seg  = elem + N_ATOMS;        // elem_index[1]
    const float* Wq   = (const float*)d_in[2];
    const float* bq   = (const float*)d_in[3];
    const float* Wk   = (const float*)d_in[4];
    const float* bk   = (const float*)d_in[5];
    const float* Wv   = (const float*)d_in[6];
    const float* bv   = (const float*)d_in[7];
    const float* Wo1  = (const float*)d_in[8];
    const float* bo1  = (const float*)d_in[9];
    const float* Wo2  = (const float*)d_in[10];
    const float* bo2  = (const float*)d_in[11];
    float* out = (float*)d_out;

    float *p_segsum, *p_h1;
    cudaGetSymbolAddress((void**)&p_segsum, g_segsum);
    cudaGetSymbolAddress((void**)&p_h1, g_h1);

    proj_gemm<<<dim3(12, 32), 256>>>(x, Wq, bq, Wk, bk, Wv, bv);
    zero_segsum<<<NG, 256>>>();
    attn_kernel<<<N_ATOMS, 256>>>(seg);
    small_gemm<<<dim3(4, 4), 256>>>(p_segsum, Wo1, bo1, p_h1, seg, 0);
    small_gemm<<<dim3(4, 4), 256>>>(p_h1, Wo2, bo2, out, seg, 1);
}